// round 14
// baseline (speedup 1.0000x reference)
#include <cuda_runtime.h>
#include <cstdint>

#define NUM_CLASSES 601
#define OUT_DIM     27
#define TAB_ELEMS   (NUM_CLASSES * OUT_DIM)            // 16227 floats = 64908 B
#define TAB_F4      ((TAB_ELEMS + 3) / 4)              // 4057 float4
#define GATHER_BLOCKS  296                             // 2 per SM (148 SMs)
#define GATHER_THREADS 1024
#define SMEM_BYTES  (TAB_F4 * 16)                      // 64912 B dynamic smem

// Softmax table in global (padded to float4 multiple for vector copy).
__device__ float4 g_tab4[TAB_F4];

// One block per class row; lane j computes exp, warp-reduce, write row (stride 27).
__global__ void build_probs_kernel(const float* __restrict__ W) {
    int r = blockIdx.x;
    int l = threadIdx.x;
    float e = 0.0f;
    if (l < OUT_DIM) e = expf(W[r * OUT_DIM + l]);
    float s = e;
    #pragma unroll
    for (int o = 16; o; o >>= 1) s += __shfl_xor_sync(0xffffffffu, s, o);
    float* tab = (float*)g_tab4;
    if (l < OUT_DIM) tab[r * OUT_DIM + l] = e / s;
}

// Grid-stride gather, 8 consecutive output floats per thread per iteration.
// Per 32B out: 1 magic-div, 2 idx LDG (L1-hot), 8 LDS, 2 independent STG.128.
// 8 < 27 so the span crosses at most one row boundary -> two row pointers,
// predicated address selects, no divergence.
__global__ void __launch_bounds__(GATHER_THREADS) gather_kernel(
        const int* __restrict__ idx, float4* __restrict__ out4,
        unsigned n8, unsigned nrows) {
    extern __shared__ float s_tab[];

    // Cooperative vectorized table copy into smem.
    {
        const float4* __restrict__ src = g_tab4;
        float4* dst = (float4*)s_tab;
        for (int i = threadIdx.x; i < TAB_F4; i += GATHER_THREADS)
            dst[i] = src[i];
    }
    __syncthreads();

    unsigned tid      = blockIdx.x * GATHER_THREADS + threadIdx.x;
    unsigned nthreads = gridDim.x * GATHER_THREADS;

    for (unsigned t = tid; t < n8; t += nthreads) {
        unsigned base = t * 8u;
        unsigned row  = base / 27u;            // single magic-multiply per 8 floats
        unsigned col  = base - row * 27u;

        int b0 = __ldg(&idx[row]);
        unsigned rown = row + 1u;
        if (rown >= nrows) rown = nrows - 1u;  // clamp tail touch
        int b1 = __ldg(&idx[rown]);

        const float* __restrict__ r0 = s_tab + (unsigned)b0 * 27u;
        const float* __restrict__ r1 = s_tab + (unsigned)b1 * 27u;

        float v[8];
        #pragma unroll
        for (int k = 0; k < 8; k++) {
            unsigned c = col + (unsigned)k;
            const float* p = (c < 27u) ? (r0 + c) : (r1 + (c - 27u));
            v[k] = *p;                          // LDS, predicated addr select
        }
        float4 o0, o1;
        o0.x = v[0]; o0.y = v[1]; o0.z = v[2]; o0.w = v[3];
        o1.x = v[4]; o1.y = v[5]; o1.z = v[6]; o1.w = v[7];
        __stcs(&out4[t * 2u + 0u], o0);        // two independent STG.128
        __stcs(&out4[t * 2u + 1u], o1);
    }
}

extern "C" void kernel_launch(void* const* d_in, const int* in_sizes, int n_in,
                              void* d_out, int out_size) {
    // Inputs: bigram_idx (int32, BATCH), W (float32, 601*27). Identify W by size.
    const int*   idx = (const int*)d_in[0];
    const float* W   = (const float*)d_in[1];
    int idx_n = in_sizes[0];
    if (n_in >= 2 && in_sizes[0] == TAB_ELEMS) {
        W     = (const float*)d_in[0];
        idx   = (const int*)d_in[1];
        idx_n = in_sizes[1];
    }
    float* out = (float*)d_out;

    // Allow >48KB dynamic smem (idempotent; host-side, not a stream op).
    static int attr_done = 0;
    if (!attr_done) {
        cudaFuncSetAttribute(gather_kernel,
                             cudaFuncAttributeMaxDynamicSharedMemorySize,
                             SMEM_BYTES);
        attr_done = 1;
    }

    // 1) 601-row softmax table.
    build_probs_kernel<<<NUM_CLASSES, 32>>>(W);

    // 2) smem-table gather, 8 floats per thread per iteration, grid-stride.
    unsigned n8 = (unsigned)(out_size / 8);
    gather_kernel<<<GATHER_BLOCKS, GATHER_THREADS, SMEM_BYTES>>>(
        idx, (float4*)out, n8, (unsigned)idx_n);
}

// round 15
// speedup vs baseline: 1.6623x; 1.6623x over previous
#include <cuda_runtime.h>
#include <cstdint>

#define NUM_CLASSES 601
#define OUT_DIM     27
#define TAB_ELEMS   (NUM_CLASSES * OUT_DIM)            // 16227 floats = 64908 B
#define TAB_F4      ((TAB_ELEMS + 3) / 4)              // 4057 float4
#define GATHER_BLOCKS  296                             // 2 per SM (148 SMs)
#define GATHER_THREADS 1024
#define SMEM_BYTES  (TAB_F4 * 16)                      // 64912 B dynamic smem

// Softmax table in global (padded to float4 multiple for vector copy).
__device__ float4 g_tab4[TAB_F4];

// One block per class row; lane j computes exp, warp-reduce, write row (stride 27).
__global__ void build_probs_kernel(const float* __restrict__ W) {
    int r = blockIdx.x;
    int l = threadIdx.x;
    float e = 0.0f;
    if (l < OUT_DIM) e = expf(W[r * OUT_DIM + l]);
    float s = e;
    #pragma unroll
    for (int o = 16; o; o >>= 1) s += __shfl_xor_sync(0xffffffffu, s, o);
    float* tab = (float*)g_tab4;
    if (l < OUT_DIM) tab[r * OUT_DIM + l] = e / s;
}

// One float4 of output for flat f4-index t. Lane-contiguous t => coalesced
// STG.128, LDS lane stride 4 banks (conflict-free within a row segment).
__device__ __forceinline__ void do_f4(const float* __restrict__ s_tab,
                                      const int* __restrict__ idx,
                                      float4* __restrict__ out4,
                                      unsigned t, unsigned last_row) {
    unsigned base = t * 4u;
    unsigned row  = base / 27u;                // magic-multiply
    unsigned col  = base - row * 27u;

    int b0 = __ldg(&idx[row]);
    unsigned rown = row < last_row ? row + 1u : last_row;
    int b1 = __ldg(&idx[rown]);

    const float* __restrict__ r0 = s_tab + (unsigned)b0 * 27u;
    const float* __restrict__ r1 = s_tab + (unsigned)b1 * 27u;

    float v[4];
    #pragma unroll
    for (int k = 0; k < 4; k++) {
        unsigned c = col + (unsigned)k;
        const float* p = (c < 27u) ? (r0 + c) : (r1 + (c - 27u));
        v[k] = *p;                              // LDS, predicated addr select
    }
    float4 o;
    o.x = v[0]; o.y = v[1]; o.z = v[2]; o.w = v[3];
    __stcs(&out4[t], o);
}

// Grid-stride gather, unrolled x2 with the two float4s separated by nthreads:
// both warp-contiguous (coalesced), but independent chains -> 2x MLP.
__global__ void __launch_bounds__(GATHER_THREADS) gather_kernel(
        const int* __restrict__ idx, float4* __restrict__ out4,
        unsigned n4, unsigned nrows) {
    extern __shared__ float s_tab[];

    // Cooperative vectorized table copy into smem.
    {
        const float4* __restrict__ src = g_tab4;
        float4* dst = (float4*)s_tab;
        for (int i = threadIdx.x; i < TAB_F4; i += GATHER_THREADS)
            dst[i] = src[i];
    }
    __syncthreads();

    const unsigned tid      = blockIdx.x * GATHER_THREADS + threadIdx.x;
    const unsigned nthreads = gridDim.x * GATHER_THREADS;
    const unsigned last_row = nrows - 1u;

    unsigned t = tid;
    for (; t + nthreads < n4; t += 2u * nthreads) {
        do_f4(s_tab, idx, out4, t,            last_row);
        do_f4(s_tab, idx, out4, t + nthreads, last_row);
    }
    if (t < n4)
        do_f4(s_tab, idx, out4, t, last_row);
}

extern "C" void kernel_launch(void* const* d_in, const int* in_sizes, int n_in,
                              void* d_out, int out_size) {
    // Inputs: bigram_idx (int32, BATCH), W (float32, 601*27). Identify W by size.
    const int*   idx = (const int*)d_in[0];
    const float* W   = (const float*)d_in[1];
    int idx_n = in_sizes[0];
    if (n_in >= 2 && in_sizes[0] == TAB_ELEMS) {
        W     = (const float*)d_in[0];
        idx   = (const int*)d_in[1];
        idx_n = in_sizes[1];
    }
    float* out = (float*)d_out;

    // Allow >48KB dynamic smem (idempotent; host-side, not a stream op).
    static int attr_done = 0;
    if (!attr_done) {
        cudaFuncSetAttribute(gather_kernel,
                             cudaFuncAttributeMaxDynamicSharedMemorySize,
                             SMEM_BYTES);
        attr_done = 1;
    }

    // 1) 601-row softmax table.
    build_probs_kernel<<<NUM_CLASSES, 32>>>(W);

    // 2) smem-table gather, float4 per thread, grid-stride unrolled x2.
    unsigned n4 = (unsigned)(out_size / 4);
    gather_kernel<<<GATHER_BLOCKS, GATHER_THREADS, SMEM_BYTES>>>(
        idx, (float4*)out, n4, (unsigned)idx_n);
}

// round 17
// speedup vs baseline: 1.6705x; 1.0049x over previous
#include <cuda_runtime.h>
#include <cstdint>

#define NUM_CLASSES 601
#define OUT_DIM     27
#define TAB_ELEMS   (NUM_CLASSES * OUT_DIM)            // 16227 floats = 64908 B
#define TAB_F4      ((TAB_ELEMS + 3) / 4)              // 4057 float4
#define GATHER_BLOCKS  296                             // 2 per SM (148 SMs)
#define GATHER_THREADS 864                             // 27 * 32: makes nthreads % 27 == 0
#define SMEM_BYTES  (TAB_F4 * 16)                      // 64912 B dynamic smem

// Softmax table in global (padded to float4 multiple for vector copy).
__device__ float4 g_tab4[TAB_F4];

// One block per class row; lane j computes exp, warp-reduce, write row (stride 27).
__global__ void build_probs_kernel(const float* __restrict__ W) {
    int r = blockIdx.x;
    int l = threadIdx.x;
    float e = 0.0f;
    if (l < OUT_DIM) e = expf(W[r * OUT_DIM + l]);
    float s = e;
    #pragma unroll
    for (int o = 16; o; o >>= 1) s += __shfl_xor_sync(0xffffffffu, s, o);
    float* tab = (float*)g_tab4;
    if (l < OUT_DIM) tab[r * OUT_DIM + l] = e / s;
}

// Grid-stride gather, one float4 per thread per iteration.
// nthreads % 27 == 0  =>  col and all crossing predicates are LOOP-INVARIANT;
// row advances by the exact constant 4*nthreads/27. Inner loop: 1 idx LDG
// (+1 predicated for the 3/27 crossing lanes), 4 LDS, 1 STG.128, ~6 ALU.
__global__ void __launch_bounds__(GATHER_THREADS) gather_kernel(
        const int* __restrict__ idx, float4* __restrict__ out4, unsigned n4) {
    extern __shared__ float s_tab[];

    // Cooperative vectorized table copy into smem.
    {
        const float4* __restrict__ src = g_tab4;
        float4* dst = (float4*)s_tab;
        for (int i = threadIdx.x; i < TAB_F4; i += GATHER_THREADS)
            dst[i] = src[i];
    }
    __syncthreads();

    const unsigned nthreads = gridDim.x * GATHER_THREADS;   // divisible by 27
    const unsigned tid      = blockIdx.x * GATHER_THREADS + threadIdx.x;
    const unsigned row_step = (4u * nthreads) / 27u;        // exact

    unsigned base = tid * 4u;
    unsigned row  = base / 27u;                 // ONE magic-div per thread
    unsigned col  = base - row * 27u;           // invariant across iterations

    // Loop-invariant crossing predicates / in-row offsets (k=0 never crosses).
    const bool f1 = (col + 1u) >= 27u;
    const bool f2 = (col + 2u) >= 27u;
    const bool f3 = (col + 3u) >= 27u;
    const unsigned o1 = f1 ? (col + 1u - 27u) : (col + 1u);
    const unsigned o2 = f2 ? (col + 2u - 27u) : (col + 2u);
    const unsigned o3 = f3 ? (col + 3u - 27u) : (col + 3u);
    const bool crosses = f3;                    // col in {24,25,26}

    const int* __restrict__ idx_p = idx + row;

    for (unsigned t = tid; t < n4; t += nthreads) {
        int b0 = __ldg(idx_p);
        const float* __restrict__ r0 = s_tab + (unsigned)b0 * 27u;
        const float* __restrict__ r1 = r0;
        if (crosses) {                           // loop-invariant predicate
            int b1 = __ldg(idx_p + 1);           // row+1 provably in-bounds
            r1 = s_tab + (unsigned)b1 * 27u;
        }
        float4 o;
        o.x = r0[col];
        o.y = (f1 ? r1 : r0)[o1];
        o.z = (f2 ? r1 : r0)[o2];
        o.w = (f3 ? r1 : r0)[o3];
        __stcs(&out4[t], o);                     // lane-contiguous STG.128
        idx_p += row_step;
    }
}

extern "C" void kernel_launch(void* const* d_in, const int* in_sizes, int n_in,
                              void* d_out, int out_size) {
    // Inputs: bigram_idx (int32, BATCH), W (float32, 601*27). Identify W by size.
    const int*   idx = (const int*)d_in[0];
    const float* W   = (const float*)d_in[1];
    if (n_in >= 2 && in_sizes[0] == TAB_ELEMS) {
        W   = (const float*)d_in[0];
        idx = (const int*)d_in[1];
    }
    float* out = (float*)d_out;

    // Allow >48KB dynamic smem (idempotent; host-side, not a stream op).
    static int attr_done = 0;
    if (!attr_done) {
        cudaFuncSetAttribute(gather_kernel,
                             cudaFuncAttributeMaxDynamicSharedMemorySize,
                             SMEM_BYTES);
        attr_done = 1;
    }

    // 1) 601-row softmax table.
    build_probs_kernel<<<NUM_CLASSES, 32>>>(W);

    // 2) smem-table gather with loop-invariant col/predicates.
    unsigned n4 = (unsigned)(out_size / 4);
    gather_kernel<<<GATHER_BLOCKS, GATHER_THREADS, SMEM_BYTES>>>(
        idx, (float4*)out, n4);
}